// round 12
// baseline (speedup 1.0000x reference)
#include <cuda_runtime.h>
#include <cuda_bf16.h>
#include <cstdint>
#include <math.h>

// ---------------- problem constants ----------------
#define BB   4
#define LL   8192
#define DD   1024
#define HH   16
#define DH   64
#define MM   (BB*LL)       // 32768
#define N3D  (3*DD)        // 3072
#define NCHUNK 8
#define CHUNK (LL/NCHUNK)  // 1024
#define NBH  (BB*HH)       // 64

// ---------------- scratch ----------------
__device__ float g_qkv[(size_t)MM * N3D];                                    // compacted: phi(q) | phi(k)*m | v*m
__device__ __nv_bfloat16 g_xhi[(size_t)MM * DD], g_xlo[(size_t)MM * DD];     // compacted x
__device__ __nv_bfloat16 g_whi[(size_t)N3D * DD], g_wlo[(size_t)N3D * DD];   // Wqkv^T [N,K]
__device__ __nv_bfloat16 g_qphi[(size_t)MM * DD], g_qplo[(size_t)MM * DD];   // q' = z*q (compacted)
__device__ __nv_bfloat16 g_mhi[(size_t)BB * DD * DD], g_mlo[(size_t)BB * DD * DD]; // M_b^T
__device__ float g_kv_part[(size_t)NCHUNK * NBH * DH * DH];
__device__ float g_ksum_part[(size_t)NCHUNK * NBH * DH];
__device__ float g_kv[(size_t)NBH * DH * DH];
__device__ float g_ksum[(size_t)NBH * DH];
// compaction state
__device__ int g_idx[MM];     // compacted j -> original global row
__device__ int g_cmask[MM];   // 1 = real row, 0 = padding
__device__ int g_npad[BB];    // active rows per batch, padded to 128

// ---------------- helpers ----------------
__device__ __forceinline__ uint32_t smem_u32(const void* p) {
    uint32_t a;
    asm("{ .reg .u64 t; cvta.to.shared.u64 t, %1; cvt.u32.u64 %0, t; }" : "=r"(a) : "l"(p));
    return a;
}
#define CP_ASYNC16(sa, ga) asm volatile("cp.async.cg.shared.global [%0], [%1], 16;" :: "r"(sa), "l"(ga))
#define CP_COMMIT()        asm volatile("cp.async.commit_group;" ::: "memory")
#define CP_WAIT(n)         asm volatile("cp.async.wait_group %0;" :: "n"(n) : "memory")

#define LDMX4(r0, r1, r2, r3, a) \
    asm volatile("ldmatrix.sync.aligned.m8n8.x4.shared.b16 {%0,%1,%2,%3}, [%4];" \
        : "=r"(r0), "=r"(r1), "=r"(r2), "=r"(r3) : "r"(a))

#define MMA16816(c, a, b0, b1) \
    asm volatile("mma.sync.aligned.m16n8k16.row.col.f32.bf16.bf16.f32 " \
        "{%0,%1,%2,%3}, {%4,%5,%6,%7}, {%8,%9}, {%0,%1,%2,%3};" \
        : "+f"((c)[0]), "+f"((c)[1]), "+f"((c)[2]), "+f"((c)[3]) \
        : "r"((a)[0]), "r"((a)[1]), "r"((a)[2]), "r"((a)[3]), "r"(b0), "r"(b1))

__device__ __forceinline__ float phi_f(float z) { return z > 0.0f ? z + 1.0f : expf(z); }

// ---------------- compaction scan (deterministic) ----------------
__global__ __launch_bounds__(1024)
void scan_kernel(const int* __restrict__ mask)
{
    __shared__ int warp_sums[32];
    const int b = blockIdx.x, tid = threadIdx.x;
    const int base = b * LL;
    const int lane = tid & 31, wid = tid >> 5;

    int vals[8], s = 0;
    #pragma unroll
    for (int j = 0; j < 8; j++) { vals[j] = mask[base + tid * 8 + j]; s += vals[j]; }

    int ssum = s;
    #pragma unroll
    for (int o = 1; o < 32; o <<= 1) {
        int v = __shfl_up_sync(0xFFFFFFFF, ssum, o);
        if (lane >= o) ssum += v;
    }
    if (lane == 31) warp_sums[wid] = ssum;
    __syncthreads();
    if (wid == 0) {
        int w = warp_sums[lane];
        #pragma unroll
        for (int o = 1; o < 32; o <<= 1) {
            int v = __shfl_up_sync(0xFFFFFFFF, w, o);
            if (lane >= o) w += v;
        }
        warp_sums[lane] = w;
    }
    __syncthreads();

    int pos = (ssum - s) + (wid > 0 ? warp_sums[wid - 1] : 0);
    #pragma unroll
    for (int j = 0; j < 8; j++) {
        if (vals[j]) {
            g_idx[base + pos] = base + tid * 8 + j;
            g_cmask[base + pos] = 1;
            pos++;
        }
    }
    __syncthreads();
    const int total = warp_sums[31];
    const int npad = (total + 127) & ~127;    // pad to 128 (GEMM M-tile)
    if (tid == 0) g_npad[b] = npad;
    for (int p = total + tid; p < npad; p += 1024) {
        g_idx[base + p] = base;
        g_cmask[base + p] = 0;
    }
}

// ---------------- zero only masked-out rows of d_out ----------------
__global__ void zero_out(const int* __restrict__ mask, float* __restrict__ out)
{
    const int r = blockIdx.x;
    if (mask[r]) return;
    ((float4*)(out + (size_t)r * DD))[threadIdx.x] = make_float4(0.f, 0.f, 0.f, 0.f);
}

// ---------------- gather + split x (compacted) ----------------
__global__ __launch_bounds__(256)
void conv_gather_x(const float* __restrict__ x)
{
    const int j = blockIdx.x;
    const int b = j >> 13;
    if ((j & (LL - 1)) >= g_npad[b]) return;
    const int tid = threadIdx.x;

    union { __nv_bfloat16 b[4]; uint2 u; } H, L;
    if (g_cmask[j]) {
        const float* src = x + (size_t)g_idx[j] * DD + tid * 4;
        float4 v = *(const float4*)src;
        float f[4] = {v.x, v.y, v.z, v.w};
        #pragma unroll
        for (int e = 0; e < 4; e++) {
            __nv_bfloat16 h = __float2bfloat16(f[e]);
            H.b[e] = h;
            L.b[e] = __float2bfloat16(f[e] - __bfloat162float(h));
        }
    } else {
        H.u = make_uint2(0, 0);
        L.u = make_uint2(0, 0);
    }
    ((uint2*)(g_xhi + (size_t)j * DD))[tid] = H.u;
    ((uint2*)(g_xlo + (size_t)j * DD))[tid] = L.u;
}

// W [R,C] row-major -> out [C,R] bf16 hi/lo
__global__ void conv_wT(const float* __restrict__ W, __nv_bfloat16* __restrict__ hi,
                        __nv_bfloat16* __restrict__ lo, int R, int Ccols)
{
    __shared__ float t[32][33];
    int cx = blockIdx.x * 32, rx = blockIdx.y * 32;
    for (int i = threadIdx.y; i < 32; i += 8)
        t[i][threadIdx.x] = W[(size_t)(rx + i) * Ccols + cx + threadIdx.x];
    __syncthreads();
    for (int i = threadIdx.y; i < 32; i += 8) {
        float v = t[threadIdx.x][i];
        __nv_bfloat16 h = __float2bfloat16(v);
        size_t o = (size_t)(cx + i) * R + rx + threadIdx.x;
        hi[o] = h;
        lo[o] = __float2bfloat16(v - __bfloat162float(h));
    }
}

// ---------------- mma.sync split-bf16 GEMM: 128x128 tile, 8 warps of 64x32, 3-stage ----------------
// C = Ahi*Bhi + Ahi*Blo + Alo*Bhi ; A [M,K] K-major, B [N,K] K-major, K=1024.
// 256 threads, warps 2m x 4n, warp tile 64x32. Packed 64B rows, XOR swizzle:
//   phys_chunk = chunk ^ ((row>>1)&3). Swizzle invariant under row+16 -> +1024B frag offsets.
#define TILE_SW 8192                    // 128 rows x 64B
#define STAGE_SW (4 * TILE_SW)          // 32768 (AH|AL|BH|BL)
#define SMEM_GEMM (3 * STAGE_SW)        // 98304, 2 CTAs/SM
#define KSTEPS 32

__device__ __forceinline__ void g_load4(uint32_t sbuf,
    const __nv_bfloat16* __restrict__ Ahi, const __nv_bfloat16* __restrict__ Alo,
    const __nv_bfloat16* __restrict__ Bhi, const __nv_bfloat16* __restrict__ Blo,
    int m0, int n0, int K, int kk, int tid)
{
    #pragma unroll
    for (int i = 0; i < 2; i++) {
        int id = tid + i * 256;              // 0..511: 128 rows x 4 chunks
        int row = id >> 2, ch = id & 3;
        uint32_t so = (uint32_t)(row * 64 + ((ch ^ ((row >> 1) & 3)) * 16));
        size_t ga = (size_t)(m0 + row) * K + kk + ch * 8;
        size_t gb = (size_t)(n0 + row) * K + kk + ch * 8;
        CP_ASYNC16(sbuf + so,               (const char*)(Ahi + ga));
        CP_ASYNC16(sbuf + TILE_SW + so,     (const char*)(Alo + ga));
        CP_ASYNC16(sbuf + 2 * TILE_SW + so, (const char*)(Bhi + gb));
        CP_ASYNC16(sbuf + 3 * TILE_SW + so, (const char*)(Blo + gb));
    }
}

template<int EPI>
__global__ __launch_bounds__(256, 2)
void gemm_bf16_split(const __nv_bfloat16* __restrict__ Ahi, const __nv_bfloat16* __restrict__ Alo,
                     const __nv_bfloat16* __restrict__ Bhi_in, const __nv_bfloat16* __restrict__ Blo_in,
                     float* __restrict__ C, int N, int K)
{
    const int m0 = blockIdx.y * 128, n0 = blockIdx.x * 128;
    if ((m0 & (LL - 1)) >= g_npad[m0 >> 13]) return;   // dead row-tile

    extern __shared__ char smem[];
    const uint32_t sb = smem_u32(smem);
    const int tid = threadIdx.x;
    const int wid = tid >> 5, lane = tid & 31;
    const int wm = wid & 1, wn = wid >> 1;   // 2m x 4n warps, 64x32 each

    const __nv_bfloat16* Bhi = Bhi_in;
    const __nv_bfloat16* Blo = Blo_in;
    if (EPI == 2) {   // per-batch B: M_b stacked [BB][N][K]
        size_t boff = (size_t)(m0 >> 13) * N * K;
        Bhi += boff;  Blo += boff;
    }

    float acc[4][4][4];
    #pragma unroll
    for (int mi = 0; mi < 4; mi++)
        #pragma unroll
        for (int j = 0; j < 4; j++)
            #pragma unroll
            for (int e = 0; e < 4; e++) acc[mi][j][e] = 0.0f;

    // swizzled ldmatrix base addresses, one per k16-half
    const int row_a = wm * 64 + (lane & 15);
    const int swa = (row_a >> 1) & 3;
    const int row_b = wn * 32 + ((lane >> 4) & 1) * 8 + (lane & 7);
    const int swb = (row_b >> 1) & 3;
    uint32_t a_off[2], b_off[2];
    #pragma unroll
    for (int c = 0; c < 2; c++) {
        a_off[c] = (uint32_t)(row_a * 64 + (((c * 2 + (lane >> 4)) ^ swa) * 16));
        b_off[c] = (uint32_t)(row_b * 64 + (((c * 2 + ((lane >> 3) & 1)) ^ swb) * 16));
    }

    // 3-stage prologue
    g_load4(sb,             Ahi, Alo, Bhi, Blo, m0, n0, K, 0, tid);  CP_COMMIT();
    g_load4(sb + STAGE_SW,  Ahi, Alo, Bhi, Blo, m0, n0, K, 32, tid); CP_COMMIT();

    for (int s = 0; s < KSTEPS; s++) {
        if (s + 2 < KSTEPS) CP_WAIT(1); else CP_WAIT(0);
        __syncthreads();
        if (s + 2 < KSTEPS) {
            g_load4(sb + ((s + 2) % 3) * STAGE_SW, Ahi, Alo, Bhi, Blo, m0, n0, K, (s + 2) * 32, tid);
            CP_COMMIT();
        }
        const uint32_t st = sb + (s % 3) * STAGE_SW;
        #pragma unroll
        for (int c = 0; c < 2; c++) {
            const uint32_t sAH = st + a_off[c];
            const uint32_t sAL = st + TILE_SW + a_off[c];
            const uint32_t sBH = st + 2 * TILE_SW + b_off[c];
            const uint32_t sBL = st + 3 * TILE_SW + b_off[c];

            uint32_t aH[4][4], bH[2][4];
            #pragma unroll
            for (int mi = 0; mi < 4; mi++)
                LDMX4(aH[mi][0], aH[mi][1], aH[mi][2], aH[mi][3], sAH + mi * 1024);
            #pragma unroll
            for (int jp = 0; jp < 2; jp++)
                LDMX4(bH[jp][0], bH[jp][1], bH[jp][2], bH[jp][3], sBH + jp * 1024);

            // aH * bH
            #pragma unroll
            for (int mi = 0; mi < 4; mi++)
                #pragma unroll
                for (int j = 0; j < 4; j++) {
                    const uint32_t* bp = bH[j >> 1];
                    if (j & 1) MMA16816(acc[mi][j], aH[mi], bp[2], bp[3]);
                    else       MMA16816(acc[mi][j], aH[mi], bp[0], bp[1]);
                }
            // aH * bL
            {
                uint32_t bL[2][4];
                #pragma unroll
                for (int jp = 0; jp < 2; jp++)
                    LDMX4(bL[jp][0], bL[jp][1], bL[jp][2], bL[jp][3], sBL + jp * 1024);
                #pragma unroll
                for (int mi = 0; mi < 4; mi++)
                    #pragma unroll
                    for (int j = 0; j < 4; j++) {
                        const uint32_t* bp = bL[j >> 1];
                        if (j & 1) MMA16816(acc[mi][j], aH[mi], bp[2], bp[3]);
                        else       MMA16816(acc[mi][j], aH[mi], bp[0], bp[1]);
                    }
            }
            // aL * bH
            {
                uint32_t aL[4][4];
                #pragma unroll
                for (int mi = 0; mi < 4; mi++)
                    LDMX4(aL[mi][0], aL[mi][1], aL[mi][2], aL[mi][3], sAL + mi * 1024);
                #pragma unroll
                for (int mi = 0; mi < 4; mi++)
                    #pragma unroll
                    for (int j = 0; j < 4; j++) {
                        const uint32_t* bp = bH[j >> 1];
                        if (j & 1) MMA16816(acc[mi][j], aL[mi], bp[2], bp[3]);
                        else       MMA16816(acc[mi][j], aL[mi], bp[0], bp[1]);
                    }
            }
        }
    }

    // epilogue: warp (wm,wn) covers rows wm*64.., cols wn*32..
    const int gr = lane >> 2, tc = lane & 3;
    const int region = n0 >> 10;
    #pragma unroll
    for (int mi = 0; mi < 4; mi++) {
        const int rbase = m0 + wm * 64 + mi * 16 + gr;
        const int cm0 = g_cmask[rbase], cm1 = g_cmask[rbase + 8];
        const float mv0 = (float)cm0, mv1 = (float)cm1;
        #pragma unroll
        for (int j = 0; j < 4; j++) {
            const int col = n0 + wn * 32 + j * 8 + tc * 2;
            float v0 = acc[mi][j][0], v1 = acc[mi][j][1];
            float v2 = acc[mi][j][2], v3 = acc[mi][j][3];
            if (EPI == 1) {
                if (region == 0)      { v0 = phi_f(v0); v1 = phi_f(v1); v2 = phi_f(v2); v3 = phi_f(v3); }
                else if (region == 1) { v0 = phi_f(v0) * mv0; v1 = phi_f(v1) * mv0;
                                        v2 = phi_f(v2) * mv1; v3 = phi_f(v3) * mv1; }
                else                  { v0 *= mv0; v1 *= mv0; v2 *= mv1; v3 *= mv1; }
                *(float2*)(C + (size_t)rbase * N + col)       = make_float2(v0, v1);
                *(float2*)(C + (size_t)(rbase + 8) * N + col) = make_float2(v2, v3);
            } else {
                if (cm0) *(float2*)(C + (size_t)g_idx[rbase] * N + col)     = make_float2(v0, v1);
                if (cm1) *(float2*)(C + (size_t)g_idx[rbase + 8] * N + col) = make_float2(v2, v3);
            }
        }
    }
}

// ---------------- Stage 2: kv / ksum partials (compacted, dynamic bound) ----------------
#define KVROWS 32
__global__ __launch_bounds__(256)
void kv_partial_kernel()
{
    const int bh = blockIdx.x, chunk = blockIdx.y;
    const int b = bh / HH, h = bh % HH;

    int bound = g_npad[b] - chunk * CHUNK;
    if (bound <= 0) {
        const int tid = threadIdx.x;
        float* out = g_kv_part + ((size_t)chunk * NBH + bh) * DH * DH;
        for (int i = tid; i < DH * DH; i += 256) out[i] = 0.0f;
        if (tid < DH) g_ksum_part[((size_t)chunk * NBH + bh) * DH + tid] = 0.0f;
        return;
    }
    if (bound > CHUNK) bound = CHUNK;
    const int NIT = bound / KVROWS;

    const int tid = threadIdx.x;
    const int ty = tid >> 4, tx = tid & 15;

    __shared__ float ks[2][KVROWS][DH];
    __shared__ float vs[2][KVROWS][DH];

    const size_t rowbase = (size_t)b * LL + (size_t)chunk * CHUNK;
    const float* kptr = g_qkv + rowbase * N3D + DD     + h * DH;
    const float* vptr = g_qkv + rowbase * N3D + 2 * DD + h * DH;

    const uint32_t ksb = smem_u32(&ks[0][0][0]);
    const uint32_t vsb = smem_u32(&vs[0][0][0]);

    auto issue = [&](int buf, int l0) {
        #pragma unroll
        for (int i = 0; i < 2; i++) {
            int id  = tid + i * 256;
            int row = id >> 4, ch = id & 15;
            uint32_t so = (uint32_t)(buf * KVROWS * DH * 4 + row * DH * 4 + ch * 16);
            CP_ASYNC16(ksb + so, (const char*)(kptr + (size_t)(l0 + row) * N3D + ch * 4));
            CP_ASYNC16(vsb + so, (const char*)(vptr + (size_t)(l0 + row) * N3D + ch * 4));
        }
        CP_COMMIT();
    };

    float acc[4][4];
    #pragma unroll
    for (int i = 0; i < 4; i++)
        #pragma unroll
        for (int j = 0; j < 4; j++) acc[i][j] = 0.0f;
    float ksacc[4] = {0.f, 0.f, 0.f, 0.f};

    issue(0, 0);
    for (int it = 0; it < NIT; it++) {
        CP_WAIT(0);
        __syncthreads();
        if (it + 1 < NIT) issue((it + 1) & 1, (it + 1) * KVROWS);
        const int buf = it & 1;
        #pragma unroll 8
        for (int r = 0; r < KVROWS; r++) {
            float kr[4], vr[4];
            *(float4*)kr = *(const float4*)&ks[buf][r][ty * 4];
            *(float4*)vr = *(const float4*)&vs[buf][r][tx * 4];
            #pragma unroll
            for (int i = 0; i < 4; i++)
                #pragma unroll
                for (int j = 0; j < 4; j++)
                    acc[i][j] += kr[i] * vr[j];
            if (tx == 0) {
                #pragma unroll
                for (int i = 0; i < 4; i++) ksacc[i] += kr[i];
            }
        }
        __syncthreads();
    }

    float* out = g_kv_part + ((size_t)chunk * NBH + bh) * DH * DH;
    #pragma unroll
    for (int i = 0; i < 4; i++)
        #pragma unroll
        for (int j = 0; j < 4; j++)
            out[(ty * 4 + i) * DH + tx * 4 + j] = acc[i][j];
    if (tx == 0) {
        float* ko = g_ksum_part + ((size_t)chunk * NBH + bh) * DH;
        #pragma unroll
        for (int i = 0; i < 4; i++) ko[ty * 4 + i] = ksacc[i];
    }
}

__global__ void kv_final_kernel()
{
    const int bh = blockIdx.x;
    for (int idx = threadIdx.x; idx < DH * DH; idx += blockDim.x) {
        float s = 0.0f;
        #pragma unroll
        for (int c = 0; c < NCHUNK; c++)
            s += g_kv_part[((size_t)c * NBH + bh) * DH * DH + idx];
        g_kv[(size_t)bh * DH * DH + idx] = s;
    }
    for (int idx = threadIdx.x; idx < DH; idx += blockDim.x) {
        float s = 0.0f;
        #pragma unroll
        for (int c = 0; c < NCHUNK; c++)
            s += g_ksum_part[((size_t)c * NBH + bh) * DH + idx];
        g_ksum[(size_t)bh * DH + idx] = s;
    }
}

// ---------------- zq (compacted) ----------------
__global__ __launch_bounds__(256)
void zq_kernel()
{
    const int r = blockIdx.x;
    const int b = r >> 13;
    if ((r & (LL - 1)) >= g_npad[b]) return;

    __shared__ float qrow[DD];
    __shared__ float zs[HH];
    const int tid = threadIdx.x;
    const int wid = tid >> 5, lane = tid & 31;

    const float* qsrc = g_qkv + (size_t)r * N3D;
    ((float4*)qrow)[tid] = ((const float4*)qsrc)[tid];
    __syncthreads();

    #pragma unroll
    for (int hh = 2 * wid; hh < 2 * wid + 2; hh++) {
        const float* ks = g_ksum + ((size_t)b * HH + hh) * DH;
        float v = qrow[hh * DH + lane] * ks[lane]
                + qrow[hh * DH + 32 + lane] * ks[32 + lane];
        #pragma unroll
        for (int o = 16; o > 0; o >>= 1)
            v += __shfl_xor_sync(0xFFFFFFFF, v, o);
        if (lane == 0) zs[hh] = 1.0f / (v + 1e-6f);
    }
    __syncthreads();

    const int c = tid * 4;
    const float z = zs[c >> 6];
    union { __nv_bfloat16 b[4]; uint2 u; } H, L;
    #pragma unroll
    for (int j = 0; j < 4; j++) {
        float v = qrow[c + j] * z;
        __nv_bfloat16 h = __float2bfloat16(v);
        H.b[j] = h;
        L.b[j] = __float2bfloat16(v - __bfloat162float(h));
    }
    ((uint2*)(g_qphi + (size_t)r * DD))[tid] = H.u;
    ((uint2*)(g_qplo + (size_t)r * DD))[tid] = L.u;
}

// ---------------- M: M_T[b][n][h*64+d] = sum_m kv[b,h,d,m] * Wout[h*64+m, n] ----------------
__global__ __launch_bounds__(256)
void m_kernel(const float* __restrict__ Wout)
{
    __shared__ float kv_s[DH * 65];
    __shared__ float w_s[DH * 64];

    const int bh = blockIdx.x;
    const int b = bh >> 4, h = bh & 15;
    const int n0 = blockIdx.y * 64;
    const int tid = threadIdx.x;

    for (int i = tid; i < DH * DH; i += 256)
        kv_s[(i >> 6) * 65 + (i & 63)] = g_kv[(size_t)bh * DH * DH + i];
    for (int i = tid; i < DH * 64; i += 256) {
        int m = i >> 6, n = i & 63;
        w_s[m * 64 + n] = Wout[(size_t)(h * DH + m) * DD + n0 + n];
    }
    __syncthreads();

    const int d = tid & 63, ng = tid >> 6;
    float acc[16];
    #pragma unroll
    for (int j = 0; j < 16; j++) acc[j] = 0.0f;

    for (int m = 0; m < DH; m++) {
        const float kvd = kv_s[d * 65 + m];
        const float* wr = w_s + m * 64 + ng * 16;
        #pragma unroll
        for (int j = 0; j < 16; j += 4) {
            float4 w4 = *(const float4*)(wr + j);
            acc[j + 0] += kvd * w4.x;
            acc[j + 1] += kvd * w4.y;
            acc[j + 2] += kvd * w4.z;
            acc[j + 3] += kvd * w4.w;
        }
    }

    #pragma unroll
    for (int j = 0; j < 16; j++) {
        const int n = n0 + ng * 16 + j;
        const size_t o = ((size_t)b * DD + n) * DD + h * DH + d;
        float v = acc[j];
        __nv_bfloat16 hh = __float2bfloat16(v);
        g_mhi[o] = hh;
        g_mlo[o] = __float2bfloat16(v - __bfloat162float(hh));
    }
}

// ---------------- launch ----------------
extern "C" void kernel_launch(void* const* d_in, const int* in_sizes, int n_in,
                              void* d_out, int out_size)
{
    (void)in_sizes; (void)n_in; (void)out_size;
    const float* x    = (const float*)d_in[0];
    const int*   mask = (const int*)  d_in[1];
    const float* Wqkv = (const float*)d_in[2];
    const float* Wout = (const float*)d_in[3];
    float* out = (float*)d_out;

    __nv_bfloat16 *xhi, *xlo, *whi, *wlo, *qphi, *qplo, *mhi, *mlo;
    float *qkv_p;
    cudaGetSymbolAddress((void**)&xhi,  g_xhi);
    cudaGetSymbolAddress((void**)&xlo,  g_xlo);
    cudaGetSymbolAddress((void**)&whi,  g_whi);
    cudaGetSymbolAddress((void**)&wlo,  g_wlo);
    cudaGetSymbolAddress((void**)&qphi, g_qphi);
    cudaGetSymbolAddress((void**)&qplo, g_qplo);
    cudaGetSymbolAddress((void**)&mhi,  g_mhi);
    cudaGetSymbolAddress((void**)&mlo,  g_mlo);
    cudaGetSymbolAddress((void**)&qkv_p, g_qkv);

    cudaFuncSetAttribute(gemm_bf16_split<1>, cudaFuncAttributeMaxDynamicSharedMemorySize, SMEM_GEMM);
    cudaFuncSetAttribute(gemm_bf16_split<2>, cudaFuncAttributeMaxDynamicSharedMemorySize, SMEM_GEMM);

    // order chosen so G1 is the 4th launch (ncu capture slot)
    scan_kernel<<<BB, 1024>>>(mask);
    conv_gather_x<<<MM, 256>>>(x);
    conv_wT<<<dim3(N3D / 32, DD / 32), dim3(32, 8)>>>(Wqkv, whi, wlo, DD, N3D);

    // G1: qkv = x_c @ Wqkv (compacted rows)
    gemm_bf16_split<1><<<dim3(N3D / 128, MM / 128), 256, SMEM_GEMM>>>(
        xhi, xlo, whi, wlo, qkv_p, N3D, DD);

    zero_out<<<MM, 256>>>(mask, out);

    // S2: kv/ksum over compacted rows
    kv_partial_kernel<<<dim3(NBH, NCHUNK), 256>>>();
    kv_final_kernel<<<NBH, 256>>>();

    // z + q' = z*q
    zq_kernel<<<MM, 256>>>();

    // M_b^T
    m_kernel<<<dim3(NBH, DD / 64), 256>>>(Wout);

    // G2: out[g_idx] = q' @ M_b (scatter)
    gemm_bf16_split<2><<<dim3(DD / 128, MM / 128), 256, SMEM_GEMM>>>(
        qphi, qplo, mhi, mlo, out, DD, DD);
}

// round 13
// speedup vs baseline: 1.2777x; 1.2777x over previous
#include <cuda_runtime.h>
#include <cuda_fp16.h>
#include <cstdint>
#include <math.h>

// ---------------- problem constants ----------------
#define BB   4
#define LL   8192
#define DD   1024
#define HH   16
#define DH   64
#define MM   (BB*LL)       // 32768
#define N3D  (3*DD)        // 3072
#define NCHUNK 8
#define CHUNK (LL/NCHUNK)  // 1024
#define NBH  (BB*HH)       // 64
#define QSCALE     65536.0f
#define QSCALE_INV (1.0f/65536.0f)

// ---------------- scratch ----------------
__device__ float g_qkv[(size_t)MM * N3D];                                  // compacted: phi(q) | phi(k)*m | v*m
__device__ __half g_xhi[(size_t)MM * DD], g_xlo[(size_t)MM * DD];          // compacted x, fp16 hi/lo
__device__ __half g_wh[(size_t)N3D * DD];                                  // Wqkv^T [N,K] fp16
__device__ __half g_qphi[(size_t)MM * DD], g_qplo[(size_t)MM * DD];        // q'*QSCALE hi/lo
__device__ __half g_mh[(size_t)BB * DD * DD];                              // M_b^T fp16
__device__ float g_kv_part[(size_t)NCHUNK * NBH * DH * DH];
__device__ float g_ksum_part[(size_t)NCHUNK * NBH * DH];
__device__ float g_kv[(size_t)NBH * DH * DH];
__device__ float g_ksum[(size_t)NBH * DH];
// compaction state
__device__ int g_idx[MM];
__device__ int g_cmask[MM];
__device__ int g_npad[BB];

// ---------------- helpers ----------------
__device__ __forceinline__ uint32_t smem_u32(const void* p) {
    uint32_t a;
    asm("{ .reg .u64 t; cvta.to.shared.u64 t, %1; cvt.u32.u64 %0, t; }" : "=r"(a) : "l"(p));
    return a;
}
#define CP_ASYNC16(sa, ga) asm volatile("cp.async.cg.shared.global [%0], [%1], 16;" :: "r"(sa), "l"(ga))
#define CP_COMMIT()        asm volatile("cp.async.commit_group;" ::: "memory")
#define CP_WAIT(n)         asm volatile("cp.async.wait_group %0;" :: "n"(n) : "memory")

#define LDMX4(r0, r1, r2, r3, a) \
    asm volatile("ldmatrix.sync.aligned.m8n8.x4.shared.b16 {%0,%1,%2,%3}, [%4];" \
        : "=r"(r0), "=r"(r1), "=r"(r2), "=r"(r3) : "r"(a))

#define MMA16816H(c, a, b0, b1) \
    asm volatile("mma.sync.aligned.m16n8k16.row.col.f32.f16.f16.f32 " \
        "{%0,%1,%2,%3}, {%4,%5,%6,%7}, {%8,%9}, {%0,%1,%2,%3};" \
        : "+f"((c)[0]), "+f"((c)[1]), "+f"((c)[2]), "+f"((c)[3]) \
        : "r"((a)[0]), "r"((a)[1]), "r"((a)[2]), "r"((a)[3]), "r"(b0), "r"(b1))

__device__ __forceinline__ float phi_f(float z) { return z > 0.0f ? z + 1.0f : expf(z); }

// ---------------- compaction scan (deterministic) ----------------
__global__ __launch_bounds__(1024)
void scan_kernel(const int* __restrict__ mask)
{
    __shared__ int warp_sums[32];
    const int b = blockIdx.x, tid = threadIdx.x;
    const int base = b * LL;
    const int lane = tid & 31, wid = tid >> 5;

    int vals[8], s = 0;
    #pragma unroll
    for (int j = 0; j < 8; j++) { vals[j] = mask[base + tid * 8 + j]; s += vals[j]; }

    int ssum = s;
    #pragma unroll
    for (int o = 1; o < 32; o <<= 1) {
        int v = __shfl_up_sync(0xFFFFFFFF, ssum, o);
        if (lane >= o) ssum += v;
    }
    if (lane == 31) warp_sums[wid] = ssum;
    __syncthreads();
    if (wid == 0) {
        int w = warp_sums[lane];
        #pragma unroll
        for (int o = 1; o < 32; o <<= 1) {
            int v = __shfl_up_sync(0xFFFFFFFF, w, o);
            if (lane >= o) w += v;
        }
        warp_sums[lane] = w;
    }
    __syncthreads();

    int pos = (ssum - s) + (wid > 0 ? warp_sums[wid - 1] : 0);
    #pragma unroll
    for (int j = 0; j < 8; j++) {
        if (vals[j]) {
            g_idx[base + pos] = base + tid * 8 + j;
            g_cmask[base + pos] = 1;
            pos++;
        }
    }
    __syncthreads();
    const int total = warp_sums[31];
    const int npad = (total + 127) & ~127;
    if (tid == 0) g_npad[b] = npad;
    for (int p = total + tid; p < npad; p += 1024) {
        g_idx[base + p] = base;
        g_cmask[base + p] = 0;
    }
}

// ---------------- zero only masked-out rows of d_out ----------------
__global__ void zero_out(const int* __restrict__ mask, float* __restrict__ out)
{
    const int r = blockIdx.x;
    if (mask[r]) return;
    ((float4*)(out + (size_t)r * DD))[threadIdx.x] = make_float4(0.f, 0.f, 0.f, 0.f);
}

// ---------------- gather + split x (compacted, fp16 hi/lo) ----------------
__global__ __launch_bounds__(256)
void conv_gather_x(const float* __restrict__ x)
{
    const int j = blockIdx.x;
    const int b = j >> 13;
    if ((j & (LL - 1)) >= g_npad[b]) return;
    const int tid = threadIdx.x;

    union { __half h[4]; uint2 u; } H, L;
    if (g_cmask[j]) {
        const float* src = x + (size_t)g_idx[j] * DD + tid * 4;
        float4 v = *(const float4*)src;
        float f[4] = {v.x, v.y, v.z, v.w};
        #pragma unroll
        for (int e = 0; e < 4; e++) {
            __half h = __float2half_rn(f[e]);
            H.h[e] = h;
            L.h[e] = __float2half_rn(f[e] - __half2float(h));
        }
    } else {
        H.u = make_uint2(0, 0);
        L.u = make_uint2(0, 0);
    }
    ((uint2*)(g_xhi + (size_t)j * DD))[tid] = H.u;
    ((uint2*)(g_xlo + (size_t)j * DD))[tid] = L.u;
}

// W [R,C] row-major -> out [C,R] fp16 (single, no lo)
__global__ void conv_wT(const float* __restrict__ W, __half* __restrict__ hi,
                        int R, int Ccols)
{
    __shared__ float t[32][33];
    int cx = blockIdx.x * 32, rx = blockIdx.y * 32;
    for (int i = threadIdx.y; i < 32; i += 8)
        t[i][threadIdx.x] = W[(size_t)(rx + i) * Ccols + cx + threadIdx.x];
    __syncthreads();
    for (int i = threadIdx.y; i < 32; i += 8)
        hi[(size_t)(cx + i) * R + rx + threadIdx.x] = __float2half_rn(t[threadIdx.x][i]);
}

// ---------------- mma.sync fp16 2-product GEMM: 128x128 tile, 4 warps of 64x64, 3-stage ----------------
// C = (Ahi + Alo) @ Bh ; A [M,K] K-major fp16 hi/lo, B [N,K] K-major fp16, K=1024.
// 128 threads, warps 2m x 2n, warp tile 64x64. Packed 64B rows, XOR swizzle.
#define TILE_SW 8192                    // 128 rows x 64B
#define STAGE_SW (3 * TILE_SW)          // 24576 (AH|AL|BH)
#define SMEM_GEMM (3 * STAGE_SW)        // 73728, 2 CTAs/SM
#define KSTEPS 32

__device__ __forceinline__ void g_load3(uint32_t sbuf,
    const __half* __restrict__ Ahi, const __half* __restrict__ Alo,
    const __half* __restrict__ Bh,
    int m0, int n0, int K, int kk, int tid)
{
    #pragma unroll
    for (int i = 0; i < 4; i++) {
        int id = tid + i * 128;              // 0..511: 128 rows x 4 chunks
        int row = id >> 2, ch = id & 3;
        uint32_t so = (uint32_t)(row * 64 + ((ch ^ ((row >> 1) & 3)) * 16));
        size_t ga = (size_t)(m0 + row) * K + kk + ch * 8;
        size_t gb = (size_t)(n0 + row) * K + kk + ch * 8;
        CP_ASYNC16(sbuf + so,               (const char*)(Ahi + ga));
        CP_ASYNC16(sbuf + TILE_SW + so,     (const char*)(Alo + ga));
        CP_ASYNC16(sbuf + 2 * TILE_SW + so, (const char*)(Bh + gb));
    }
}

template<int EPI>
__global__ __launch_bounds__(128, 2)
void gemm_fp16_split(const __half* __restrict__ Ahi, const __half* __restrict__ Alo,
                     const __half* __restrict__ Bh_in,
                     float* __restrict__ C, int N, int K)
{
    const int m0 = blockIdx.y * 128, n0 = blockIdx.x * 128;
    if ((m0 & (LL - 1)) >= g_npad[m0 >> 13]) return;   // dead row-tile

    extern __shared__ char smem[];
    const uint32_t sb = smem_u32(smem);
    const int tid = threadIdx.x;
    const int wid = tid >> 5, lane = tid & 31;
    const int wm = wid & 1, wn = wid >> 1;   // 2m x 2n warps, 64x64 each

    const __half* Bh = Bh_in;
    if (EPI == 2) {   // per-batch B: M_b stacked [BB][N][K]
        Bh += (size_t)(m0 >> 13) * N * K;
    }

    float acc[4][8][4];
    #pragma unroll
    for (int mi = 0; mi < 4; mi++)
        #pragma unroll
        for (int j = 0; j < 8; j++)
            #pragma unroll
            for (int e = 0; e < 4; e++) acc[mi][j][e] = 0.0f;

    // swizzled ldmatrix base addresses, one per k16-half
    const int row_a = wm * 64 + (lane & 15);
    const int swa = (row_a >> 1) & 3;
    const int row_b = wn * 64 + ((lane >> 4) & 1) * 8 + (lane & 7);
    const int swb = (row_b >> 1) & 3;
    uint32_t a_off[2], b_off[2];
    #pragma unroll
    for (int c = 0; c < 2; c++) {
        a_off[c] = (uint32_t)(row_a * 64 + (((c * 2 + (lane >> 4)) ^ swa) * 16));
        b_off[c] = (uint32_t)(row_b * 64 + (((c * 2 + ((lane >> 3) & 1)) ^ swb) * 16));
    }

    // 3-stage prologue
    g_load3(sb,             Ahi, Alo, Bh, m0, n0, K, 0, tid);  CP_COMMIT();
    g_load3(sb + STAGE_SW,  Ahi, Alo, Bh, m0, n0, K, 32, tid); CP_COMMIT();

    for (int s = 0; s < KSTEPS; s++) {
        if (s + 2 < KSTEPS) CP_WAIT(1); else CP_WAIT(0);
        __syncthreads();
        if (s + 2 < KSTEPS) {
            g_load3(sb + ((s + 2) % 3) * STAGE_SW, Ahi, Alo, Bh, m0, n0, K, (s + 2) * 32, tid);
            CP_COMMIT();
        }
        const uint32_t st = sb + (s % 3) * STAGE_SW;
        #pragma unroll
        for (int c = 0; c < 2; c++) {
            const uint32_t sAH = st + a_off[c];
            const uint32_t sAL = st + TILE_SW + a_off[c];
            const uint32_t sBH = st + 2 * TILE_SW + b_off[c];

            uint32_t aH[4][4], bH[4][4];
            #pragma unroll
            for (int mi = 0; mi < 4; mi++)
                LDMX4(aH[mi][0], aH[mi][1], aH[mi][2], aH[mi][3], sAH + mi * 1024);
            #pragma unroll
            for (int jp = 0; jp < 4; jp++)
                LDMX4(bH[jp][0], bH[jp][1], bH[jp][2], bH[jp][3], sBH + jp * 1024);

            // aH * bH
            #pragma unroll
            for (int mi = 0; mi < 4; mi++)
                #pragma unroll
                for (int j = 0; j < 8; j++) {
                    const uint32_t* bp = bH[j >> 1];
                    if (j & 1) MMA16816H(acc[mi][j], aH[mi], bp[2], bp[3]);
                    else       MMA16816H(acc[mi][j], aH[mi], bp[0], bp[1]);
                }
            // aL * bH
            {
                uint32_t aL[4][4];
                #pragma unroll
                for (int mi = 0; mi < 4; mi++)
                    LDMX4(aL[mi][0], aL[mi][1], aL[mi][2], aL[mi][3], sAL + mi * 1024);
                #pragma unroll
                for (int mi = 0; mi < 4; mi++)
                    #pragma unroll
                    for (int j = 0; j < 8; j++) {
                        const uint32_t* bp = bH[j >> 1];
                        if (j & 1) MMA16816H(acc[mi][j], aL[mi], bp[2], bp[3]);
                        else       MMA16816H(acc[mi][j], aL[mi], bp[0], bp[1]);
                    }
            }
        }
    }

    // epilogue: warp (wm,wn) covers rows wm*64.., cols wn*64..
    const int gr = lane >> 2, tc = lane & 3;
    const int region = n0 >> 10;
    #pragma unroll
    for (int mi = 0; mi < 4; mi++) {
        const int rbase = m0 + wm * 64 + mi * 16 + gr;
        const int cm0 = g_cmask[rbase], cm1 = g_cmask[rbase + 8];
        const float mv0 = (float)cm0, mv1 = (float)cm1;
        #pragma unroll
        for (int j = 0; j < 8; j++) {
            const int col = n0 + wn * 64 + j * 8 + tc * 2;
            float v0 = acc[mi][j][0], v1 = acc[mi][j][1];
            float v2 = acc[mi][j][2], v3 = acc[mi][j][3];
            if (EPI == 1) {
                if (region == 0)      { v0 = phi_f(v0); v1 = phi_f(v1); v2 = phi_f(v2); v3 = phi_f(v3); }
                else if (region == 1) { v0 = phi_f(v0) * mv0; v1 = phi_f(v1) * mv0;
                                        v2 = phi_f(v2) * mv1; v3 = phi_f(v3) * mv1; }
                else                  { v0 *= mv0; v1 *= mv0; v2 *= mv1; v3 *= mv1; }
                *(float2*)(C + (size_t)rbase * N + col)       = make_float2(v0, v1);
                *(float2*)(C + (size_t)(rbase + 8) * N + col) = make_float2(v2, v3);
            } else {   // EPI==2: scatter, undo q' scaling
                v0 *= QSCALE_INV; v1 *= QSCALE_INV; v2 *= QSCALE_INV; v3 *= QSCALE_INV;
                if (cm0) *(float2*)(C + (size_t)g_idx[rbase] * N + col)     = make_float2(v0, v1);
                if (cm1) *(float2*)(C + (size_t)g_idx[rbase + 8] * N + col) = make_float2(v2, v3);
            }
        }
    }
}

// ---------------- Stage 2: kv / ksum partials (compacted, dynamic bound) ----------------
#define KVROWS 32
__global__ __launch_bounds__(256)
void kv_partial_kernel()
{
    const int bh = blockIdx.x, chunk = blockIdx.y;
    const int b = bh / HH, h = bh % HH;

    int bound = g_npad[b] - chunk * CHUNK;
    if (bound <= 0) {
        const int tid = threadIdx.x;
        float* out = g_kv_part + ((size_t)chunk * NBH + bh) * DH * DH;
        for (int i = tid; i < DH * DH; i += 256) out[i] = 0.0f;
        if (tid < DH) g_ksum_part[((size_t)chunk * NBH + bh) * DH + tid] = 0.0f;
        return;
    }
    if (bound > CHUNK) bound = CHUNK;
    const int NIT = bound / KVROWS;

    const int tid = threadIdx.x;
    const int ty = tid >> 4, tx = tid & 15;

    __shared__ float ks[2][KVROWS][DH];
    __shared__ float vs[2][KVROWS][DH];

    const size_t rowbase = (size_t)b * LL + (size_t)chunk * CHUNK;
    const float* kptr = g_qkv + rowbase * N3D + DD     + h * DH;
    const float* vptr = g_qkv + rowbase * N3D + 2 * DD + h * DH;

    const uint32_t ksb = smem_u32(&ks[0][0][0]);
    const uint32_t vsb = smem_u32(&vs[0][0][0]);

    auto issue = [&](int buf, int l0) {
        #pragma unroll
        for (int i = 0; i < 2; i++) {
            int id  = tid + i * 256;
            int row = id >> 4, ch = id & 15;
            uint32_t so = (uint32_t)(buf * KVROWS * DH * 4 + row * DH * 4 + ch * 16);
            CP_ASYNC16(ksb + so, (const char*)(kptr + (size_t)(l0 + row) * N3D + ch * 4));
            CP_ASYNC16(vsb + so, (const char*)(vptr + (size_t)(l0 + row) * N3D + ch * 4));
        }
        CP_COMMIT();
    };

    float acc[4][4];
    #pragma unroll
    for (int i = 0; i < 4; i++)
        #pragma unroll
        for (int j = 0; j < 4; j++) acc[i][j] = 0.0f;
    float ksacc[4] = {0.f, 0.f, 0.f, 0.f};

    issue(0, 0);
    for (int it = 0; it < NIT; it++) {
        CP_WAIT(0);
        __syncthreads();
        if (it + 1 < NIT) issue((it + 1) & 1, (it + 1) * KVROWS);
        const int buf = it & 1;
        #pragma unroll 8
        for (int r = 0; r < KVROWS; r++) {
            float kr[4], vr[4];
            *(float4*)kr = *(const float4*)&ks[buf][r][ty * 4];
            *(float4*)vr = *(const float4*)&vs[buf][r][tx * 4];
            #pragma unroll
            for (int i = 0; i < 4; i++)
                #pragma unroll
                for (int j = 0; j < 4; j++)
                    acc[i][j] += kr[i] * vr[j];
            if (tx == 0) {
                #pragma unroll
                for (int i = 0; i < 4; i++) ksacc[i] += kr[i];
            }
        }
        __syncthreads();
    }

    float* out = g_kv_part + ((size_t)chunk * NBH + bh) * DH * DH;
    #pragma unroll
    for (int i = 0; i < 4; i++)
        #pragma unroll
        for (int j = 0; j < 4; j++)
            out[(ty * 4 + i) * DH + tx * 4 + j] = acc[i][j];
    if (tx == 0) {
        float* ko = g_ksum_part + ((size_t)chunk * NBH + bh) * DH;
        #pragma unroll
        for (int i = 0; i < 4; i++) ko[ty * 4 + i] = ksacc[i];
    }
}

__global__ void kv_final_kernel()
{
    const int bh = blockIdx.x;
    for (int idx = threadIdx.x; idx < DH * DH; idx += blockDim.x) {
        float s = 0.0f;
        #pragma unroll
        for (int c = 0; c < NCHUNK; c++)
            s += g_kv_part[((size_t)c * NBH + bh) * DH * DH + idx];
        g_kv[(size_t)bh * DH * DH + idx] = s;
    }
    for (int idx = threadIdx.x; idx < DH; idx += blockDim.x) {
        float s = 0.0f;
        #pragma unroll
        for (int c = 0; c < NCHUNK; c++)
            s += g_ksum_part[((size_t)c * NBH + bh) * DH + idx];
        g_ksum[(size_t)bh * DH + idx] = s;
    }
}

// ---------------- zq (compacted): q' = z*q*QSCALE -> fp16 hi/lo ----------------
__global__ __launch_bounds__(256)
void zq_kernel()
{
    const int r = blockIdx.x;
    const int b = r >> 13;
    if ((r & (LL - 1)) >= g_npad[b]) return;

    __shared__ float qrow[DD];
    __shared__ float zs[HH];
    const int tid = threadIdx.x;
    const int wid = tid >> 5, lane = tid & 31;

    const float* qsrc = g_qkv + (size_t)r * N3D;
    ((float4*)qrow)[tid] = ((const float4*)qsrc)[tid];
    __syncthreads();

    #pragma unroll
    for (int hh = 2 * wid; hh < 2 * wid + 2; hh++) {
        const float* ks = g_ksum + ((size_t)b * HH + hh) * DH;
        float v = qrow[hh * DH + lane] * ks[lane]
                + qrow[hh * DH + 32 + lane] * ks[32 + lane];
        #pragma unroll
        for (int o = 16; o > 0; o >>= 1)
            v += __shfl_xor_sync(0xFFFFFFFF, v, o);
        if (lane == 0) zs[hh] = QSCALE / (v + 1e-6f);
    }
    __syncthreads();

    const int c = tid * 4;
    const float z = zs[c >> 6];
    union { __half h[4]; uint2 u; } H, L;
    #pragma unroll
    for (int j = 0; j < 4; j++) {
        float v = qrow[c + j] * z;
        __half h = __float2half_rn(v);
        H.h[j] = h;
        L.h[j] = __float2half_rn(v - __half2float(h));
    }
    ((uint2*)(g_qphi + (size_t)r * DD))[tid] = H.u;
    ((uint2*)(g_qplo + (size_t)r * DD))[tid] = L.u;
}

// ---------------- M: M_T[b][n][h*64+d] = sum_m kv[b,h,d,m] * Wout[h*64+m, n] -> fp16 ----------------
__global__ __launch_bounds__(256)
void m_kernel(const float* __restrict__ Wout)
{
    __shared__ float kv_s[DH * 65];
    __shared__ float w_s[DH * 64];

    const int bh = blockIdx.x;
    const int b = bh >> 4, h = bh & 15;
    const int n0 = blockIdx.y * 64;
    const int tid = threadIdx.x;

    for (int i = tid; i < DH * DH; i += 256)
        kv_s[(i >> 6) * 65 + (i & 63)] = g_kv[(size_t)bh * DH * DH + i];
    for (int i = tid; i < DH * 64; i += 256) {
        int m = i >> 6, n = i & 63;
        w_s[m * 64 + n] = Wout[(size_t)(h * DH + m) * DD + n0 + n];
    }
    __syncthreads();

    const int d = tid & 63, ng = tid >> 6;
    float acc[16];
    #pragma unroll
    for (int j = 0; j < 16; j++) acc[j] = 0.0f;

    for (int m = 0; m < DH; m++) {
        const float kvd = kv_s[d * 65 + m];
        const float* wr = w_s + m * 64 + ng * 16;
        #pragma unroll
        for (int j = 0; j < 16; j += 4) {
            float4 w4 = *(const float4*)(wr + j);
            acc[j + 0] += kvd * w4.x;
            acc[j + 1] += kvd * w4.y;
            acc[j + 2] += kvd * w4.z;
            acc[j + 3] += kvd * w4.w;
        }
    }

    #pragma unroll
    for (int j = 0; j < 16; j++) {
        const int n = n0 + ng * 16 + j;
        g_mh[((size_t)b * DD + n) * DD + h * DH + d] = __float2half_rn(acc[j]);
    }
}

// ---------------- launch ----------------
extern "C" void kernel_launch(void* const* d_in, const int* in_sizes, int n_in,
                              void* d_out, int out_size)
{
    (void)in_sizes; (void)n_in; (void)out_size;
    const float* x    = (const float*)d_in[0];
    const int*   mask = (const int*)  d_in[1];
    const float* Wqkv = (const float*)d_in[2];
    const float* Wout = (const float*)d_in[3];
    float* out = (float*)d_out;

    __half *xhi, *xlo, *wh, *qphi, *qplo, *mh;
    float *qkv_p;
    cudaGetSymbolAddress((void**)&xhi,  g_xhi);
    cudaGetSymbolAddress((void**)&xlo,  g_xlo);
    cudaGetSymbolAddress((void**)&wh,   g_wh);
    cudaGetSymbolAddress((void**)&qphi, g_qphi);
    cudaGetSymbolAddress((void**)&qplo, g_qplo);
    cudaGetSymbolAddress((void**)&mh,   g_mh);
    cudaGetSymbolAddress((void**)&qkv_p, g_qkv);

    cudaFuncSetAttribute(gemm_fp16_split<1>, cudaFuncAttributeMaxDynamicSharedMemorySize, SMEM_GEMM);
    cudaFuncSetAttribute(gemm_fp16_split<2>, cudaFuncAttributeMaxDynamicSharedMemorySize, SMEM_GEMM);

    // order chosen so G1 is the 4th launch (ncu capture slot)
    scan_kernel<<<BB, 1024>>>(mask);
    conv_gather_x<<<MM, 256>>>(x);
    conv_wT<<<dim3(N3D / 32, DD / 32), dim3(32, 8)>>>(Wqkv, wh, DD, N3D);

    // G1: qkv = x_c @ Wqkv (compacted rows)
    gemm_fp16_split<1><<<dim3(N3D / 128, MM / 128), 128, SMEM_GEMM>>>(
        xhi, xlo, wh, qkv_p, N3D, DD);

    zero_out<<<MM, 256>>>(mask, out);

    // S2: kv/ksum over compacted rows
    kv_partial_kernel<<<dim3(NBH, NCHUNK), 256>>>();
    kv_final_kernel<<<NBH, 256>>>();

    // z + q' = z*q*QSCALE
    zq_kernel<<<MM, 256>>>();

    // M_b^T -> fp16
    m_kernel<<<dim3(NBH, DD / 64), 256>>>(Wout);

    // G2: out[g_idx] = (q' @ M_b) * QSCALE_INV (scatter)
    gemm_fp16_split<2><<<dim3(DD / 128, MM / 128), 128, SMEM_GEMM>>>(
        qphi, qplo, mh, out, DD, DD);
}

// round 15
// speedup vs baseline: 1.8615x; 1.4569x over previous
#include <cuda_runtime.h>
#include <cuda_fp16.h>
#include <cstdint>
#include <math.h>

// ---------------- problem constants ----------------
#define BB   4
#define LL   8192
#define DD   1024
#define HH   16
#define DH   64
#define MM   (BB*LL)       // 32768
#define N3D  (3*DD)        // 3072
#define NCHUNK 8
#define CHUNK (LL/NCHUNK)  // 1024
#define NBH  (BB*HH)       // 64
#define QSCALE     65536.0f
#define QSCALE_INV (1.0f/65536.0f)

// ---------------- scratch ----------------
__device__ float g_qkv[(size_t)MM * N3D];                                  // compacted: phi(q) | phi(k)*m | v*m
__device__ __half g_xh[(size_t)MM * DD];                                   // compacted x fp16
__device__ __half g_wh[(size_t)N3D * DD];                                  // Wqkv^T [N,K] fp16
__device__ __half g_qph[(size_t)MM * DD];                                  // q'*QSCALE fp16
__device__ __half g_mh[(size_t)BB * DD * DD];                              // M_b^T fp16
__device__ float g_kv_part[(size_t)NCHUNK * NBH * DH * DH];
__device__ float g_ksum_part[(size_t)NCHUNK * NBH * DH];
__device__ float g_kv[(size_t)NBH * DH * DH];
__device__ float g_ksum[(size_t)NBH * DH];
// compaction state
__device__ int g_idx[MM];
__device__ int g_cmask[MM];
__device__ int g_npad[BB];

// ---------------- helpers ----------------
__device__ __forceinline__ uint32_t smem_u32(const void* p) {
    uint32_t a;
    asm("{ .reg .u64 t; cvta.to.shared.u64 t, %1; cvt.u32.u64 %0, t; }" : "=r"(a) : "l"(p));
    return a;
}
#define CP_ASYNC16(sa, ga) asm volatile("cp.async.cg.shared.global [%0], [%1], 16;" :: "r"(sa), "l"(ga))
#define CP_COMMIT()        asm volatile("cp.async.commit_group;" ::: "memory")
#define CP_WAIT(n)         asm volatile("cp.async.wait_group %0;" :: "n"(n) : "memory")

#define LDMX4(r0, r1, r2, r3, a) \
    asm volatile("ldmatrix.sync.aligned.m8n8.x4.shared.b16 {%0,%1,%2,%3}, [%4];" \
        : "=r"(r0), "=r"(r1), "=r"(r2), "=r"(r3) : "r"(a))

#define MMA16816H(c, a, b0, b1) \
    asm volatile("mma.sync.aligned.m16n8k16.row.col.f32.f16.f16.f32 " \
        "{%0,%1,%2,%3}, {%4,%5,%6,%7}, {%8,%9}, {%0,%1,%2,%3};" \
        : "+f"((c)[0]), "+f"((c)[1]), "+f"((c)[2]), "+f"((c)[3]) \
        : "r"((a)[0]), "r"((a)[1]), "r"((a)[2]), "r"((a)[3]), "r"(b0), "r"(b1))

__device__ __forceinline__ float phi_f(float z) { return z > 0.0f ? z + 1.0f : expf(z); }

// ---------------- compaction scan (deterministic) ----------------
__global__ __launch_bounds__(1024)
void scan_kernel(const int* __restrict__ mask)
{
    __shared__ int warp_sums[32];
    const int b = blockIdx.x, tid = threadIdx.x;
    const int base = b * LL;
    const int lane = tid & 31, wid = tid >> 5;

    int vals[8], s = 0;
    #pragma unroll
    for (int j = 0; j < 8; j++) { vals[j] = mask[base + tid * 8 + j]; s += vals[j]; }

    int ssum = s;
    #pragma unroll
    for (int o = 1; o < 32; o <<= 1) {
        int v = __shfl_up_sync(0xFFFFFFFF, ssum, o);
        if (lane >= o) ssum += v;
    }
    if (lane == 31) warp_sums[wid] = ssum;
    __syncthreads();
    if (wid == 0) {
        int w = warp_sums[lane];
        #pragma unroll
        for (int o = 1; o < 32; o <<= 1) {
            int v = __shfl_up_sync(0xFFFFFFFF, w, o);
            if (lane >= o) w += v;
        }
        warp_sums[lane] = w;
    }
    __syncthreads();

    int pos = (ssum - s) + (wid > 0 ? warp_sums[wid - 1] : 0);
    #pragma unroll
    for (int j = 0; j < 8; j++) {
        if (vals[j]) {
            g_idx[base + pos] = base + tid * 8 + j;
            g_cmask[base + pos] = 1;
            pos++;
        }
    }
    __syncthreads();
    const int total = warp_sums[31];
    const int npad = (total + 127) & ~127;
    if (tid == 0) g_npad[b] = npad;
    for (int p = total + tid; p < npad; p += 1024) {
        g_idx[base + p] = base;
        g_cmask[base + p] = 0;
    }
}

// ---------------- zero only masked-out rows of d_out ----------------
__global__ void zero_out(const int* __restrict__ mask, float* __restrict__ out)
{
    const int r = blockIdx.x;
    if (mask[r]) return;
    ((float4*)(out + (size_t)r * DD))[threadIdx.x] = make_float4(0.f, 0.f, 0.f, 0.f);
}

// ---------------- gather x -> fp16 (compacted) ----------------
__global__ __launch_bounds__(256)
void conv_gather_x(const float* __restrict__ x)
{
    const int j = blockIdx.x;
    const int b = j >> 13;
    if ((j & (LL - 1)) >= g_npad[b]) return;
    const int tid = threadIdx.x;

    union { __half h[4]; uint2 u; } H;
    if (g_cmask[j]) {
        const float* src = x + (size_t)g_idx[j] * DD + tid * 4;
        float4 v = *(const float4*)src;
        H.h[0] = __float2half_rn(v.x); H.h[1] = __float2half_rn(v.y);
        H.h[2] = __float2half_rn(v.z); H.h[3] = __float2half_rn(v.w);
    } else {
        H.u = make_uint2(0, 0);
    }
    ((uint2*)(g_xh + (size_t)j * DD))[tid] = H.u;
}

// W [R,C] row-major -> out [C,R] fp16
__global__ void conv_wT(const float* __restrict__ W, __half* __restrict__ hi,
                        int R, int Ccols)
{
    __shared__ float t[32][33];
    int cx = blockIdx.x * 32, rx = blockIdx.y * 32;
    for (int i = threadIdx.y; i < 32; i += 8)
        t[i][threadIdx.x] = W[(size_t)(rx + i) * Ccols + cx + threadIdx.x];
    __syncthreads();
    for (int i = threadIdx.y; i < 32; i += 8)
        hi[(size_t)(cx + i) * R + rx + threadIdx.x] = __float2half_rn(t[threadIdx.x][i]);
}

// ---------------- mma.sync fp16 1-product GEMM: 128x128 tile, 4 warps of 64x64, 4-stage ----------------
// C = A @ B ; A [M,K] K-major fp16, B [N,K] K-major fp16, K=1024.
// 128 threads, warps 2m x 2n, warp tile 64x64. Packed 64B rows, XOR swizzle:
//   phys_chunk = chunk ^ ((row>>1)&3); invariant under row+16 -> +1024B frag offsets.
#define TILE_SW 8192                    // 128 rows x 64B
#define STAGE_SW (2 * TILE_SW)          // 16384 (A|B)
#define SMEM_GEMM (4 * STAGE_SW)        // 65536, 2 CTAs/SM
#define KSTEPS 32

__device__ __forceinline__ void g_load2(uint32_t sbuf,
    const __half* __restrict__ Ah, const __half* __restrict__ Bh,
    int m0, int n0, int K, int kk, int tid)
{
    #pragma unroll
    for (int i = 0; i < 4; i++) {
        int id = tid + i * 128;              // 0..511: 128 rows x 4 chunks
        int row = id >> 2, ch = id & 3;
        uint32_t so = (uint32_t)(row * 64 + ((ch ^ ((row >> 1) & 3)) * 16));
        CP_ASYNC16(sbuf + so,           (const char*)(Ah + (size_t)(m0 + row) * K + kk + ch * 8));
        CP_ASYNC16(sbuf + TILE_SW + so, (const char*)(Bh + (size_t)(n0 + row) * K + kk + ch * 8));
    }
}

template<int EPI>
__global__ __launch_bounds__(128, 2)
void gemm_fp16(const __half* __restrict__ Ah, const __half* __restrict__ Bh_in,
               float* __restrict__ C, int N, int K)
{
    const int m0 = blockIdx.y * 128, n0 = blockIdx.x * 128;
    if ((m0 & (LL - 1)) >= g_npad[m0 >> 13]) return;   // dead row-tile

    extern __shared__ char smem[];
    const uint32_t sb = smem_u32(smem);
    const int tid = threadIdx.x;
    const int wid = tid >> 5, lane = tid & 31;
    const int wm = wid & 1, wn = wid >> 1;   // 2m x 2n warps, 64x64 each

    const __half* Bh = Bh_in;
    if (EPI == 2) {   // per-batch B: M_b stacked [BB][N][K]
        Bh += (size_t)(m0 >> 13) * N * K;
    }

    float acc[4][8][4];
    #pragma unroll
    for (int mi = 0; mi < 4; mi++)
        #pragma unroll
        for (int j = 0; j < 8; j++)
            #pragma unroll
            for (int e = 0; e < 4; e++) acc[mi][j][e] = 0.0f;

    // swizzled ldmatrix base addresses, one per k16-half
    const int row_a = wm * 64 + (lane & 15);
    const int swa = (row_a >> 1) & 3;
    const int row_b = wn * 64 + ((lane >> 4) & 1) * 8 + (lane & 7);
    const int swb = (row_b >> 1) & 3;
    uint32_t a_off[2], b_off[2];
    #pragma unroll
    for (int c = 0; c < 2; c++) {
        a_off[c] = (uint32_t)(row_a * 64 + (((c * 2 + (lane >> 4)) ^ swa) * 16));
        b_off[c] = (uint32_t)(row_b * 64 + (((c * 2 + ((lane >> 3) & 1)) ^ swb) * 16));
    }

    // 4-stage prologue (3 stages in flight)
    g_load2(sb,                Ah, Bh, m0, n0, K, 0, tid);  CP_COMMIT();
    g_load2(sb + STAGE_SW,     Ah, Bh, m0, n0, K, 32, tid); CP_COMMIT();
    g_load2(sb + 2 * STAGE_SW, Ah, Bh, m0, n0, K, 64, tid); CP_COMMIT();

    for (int s = 0; s < KSTEPS; s++) {
        if (s + 2 < KSTEPS)      CP_WAIT(2);
        else if (s + 1 < KSTEPS) CP_WAIT(1);
        else                     CP_WAIT(0);
        __syncthreads();
        if (s + 3 < KSTEPS) {
            g_load2(sb + ((s + 3) & 3) * STAGE_SW, Ah, Bh, m0, n0, K, (s + 3) * 32, tid);
            CP_COMMIT();
        }
        const uint32_t st = sb + (s & 3) * STAGE_SW;
        #pragma unroll
        for (int c = 0; c < 2; c++) {
            const uint32_t sA = st + a_off[c];
            const uint32_t sB = st + TILE_SW + b_off[c];

            uint32_t a[4][4], b[4][4];
            #pragma unroll
            for (int mi = 0; mi < 4; mi++)
                LDMX4(a[mi][0], a[mi][1], a[mi][2], a[mi][3], sA + mi * 1024);
            #pragma unroll
            for (int jp = 0; jp < 4; jp++)
                LDMX4(b[jp][0], b[jp][1], b[jp][2], b[jp][3], sB + jp * 1024);

            #pragma unroll
            for (int mi = 0; mi < 4; mi++)
                #pragma unroll
                for (int j = 0; j < 8; j++) {
                    const uint32_t* bp = b[j >> 1];
                    if (j & 1) MMA16816H(acc[mi][j], a[mi], bp[2], bp[3]);
                    else       MMA16816H(acc[mi][j], a[mi], bp[0], bp[1]);
                }
        }
    }

    // epilogue: warp (wm,wn) covers rows wm*64.., cols wn*64..
    const int gr = lane >> 2, tc = lane & 3;
    const int region = n0 >> 10;
    #pragma unroll
    for (int mi = 0; mi < 4; mi++) {
        const int rbase = m0 + wm * 64 + mi * 16 + gr;
        const int cm0 = g_cmask[rbase], cm1 = g_cmask[rbase + 8];
        const float mv0 = (float)cm0, mv1 = (float)cm1;
        #pragma unroll
        for (int j = 0; j < 8; j++) {
            const int col = n0 + wn * 64 + j * 8 + tc * 2;
            float v0 = acc[mi][j][0], v1 = acc[mi][j][1];
            float v2 = acc[mi][j][2], v3 = acc[mi][j][3];
            if (EPI == 1) {
                if (region == 0)      { v0 = phi_f(v0); v1 = phi_f(v1); v2 = phi_f(v2); v3 = phi_f(v3); }
                else if (region == 1) { v0 = phi_f(v0) * mv0; v1 = phi_f(v1) * mv0;
                                        v2 = phi_f(v2) * mv1; v3 = phi_f(v3) * mv1; }
                else                  { v0 *= mv0; v1 *= mv0; v2 *= mv1; v3 *= mv1; }
                *(float2*)(C + (size_t)rbase * N + col)       = make_float2(v0, v1);
                *(float2*)(C + (size_t)(rbase + 8) * N + col) = make_float2(v2, v3);
            } else {   // EPI==2: scatter, undo q' scaling
                v0 *= QSCALE_INV; v1 *= QSCALE_INV; v2 *= QSCALE_INV; v3 *= QSCALE_INV;
                if (cm0) *(float2*)(C + (size_t)g_idx[rbase] * N + col)     = make_float2(v0, v1);
                if (cm1) *(float2*)(C + (size_t)g_idx[rbase + 8] * N + col) = make_float2(v2, v3);
            }
        }
    }
}

// ---------------- Stage 2: kv / ksum partials (compacted, dynamic bound) ----------------
#define KVROWS 32
__global__ __launch_bounds__(256)
void kv_partial_kernel()
{
    const int bh = blockIdx.x, chunk = blockIdx.y;
    const int b = bh / HH, h = bh % HH;

    int bound = g_npad[b] - chunk * CHUNK;
    if (bound <= 0) {
        const int tid = threadIdx.x;
        float* out = g_kv_part + ((size_t)chunk * NBH + bh) * DH * DH;
        for (int i = tid; i < DH * DH; i += 256) out[i] = 0.0f;
        if (tid < DH) g_ksum_part[((size_t)chunk * NBH + bh) * DH + tid] = 0.0f;
        return;
    }
    if (bound > CHUNK) bound = CHUNK;
    const int NIT = bound / KVROWS;

    const int tid = threadIdx.x;
    const int ty = tid >> 4, tx = tid & 15;

    __shared__ float ks[2][KVROWS][DH];
    __shared__ float vs[2][KVROWS][DH];

    const size_t rowbase = (size_t)b * LL + (size_t)chunk * CHUNK;
    const float* kptr = g_qkv + rowbase * N3D + DD     + h * DH;
    const float* vptr = g_qkv + rowbase * N3D + 2 * DD + h * DH;

    const uint32_t ksb = smem_u32(&ks[0][0][0]);
    const uint32_t vsb = smem_u32(&vs[0][0][0]);

    auto issue = [&](int buf, int l0) {
        #pragma unroll
        for (int i = 0; i < 2; i++) {
            int id  = tid + i * 256;
            int row = id >> 4, ch = id & 15;
            uint32_t so = (uint32_t)(buf * KVROWS * DH * 4 + row * DH * 4 + ch * 16);
            CP_ASYNC16(ksb + so, (const char*)(kptr + (size_t)(l0 + row) * N3D + ch * 4));
            CP_ASYNC16(vsb + so, (const char*)(vptr + (size_t)(l0 + row) * N3D + ch * 4));
        }
        CP_COMMIT();
    };

    float acc[4][4];
    #pragma unroll
    for (int i = 0; i < 4; i++)
        #pragma unroll
        for (int j = 0; j < 4; j++) acc[i][j] = 0.0f;
    float ksacc[4] = {0.f, 0.f, 0.f, 0.f};

    issue(0, 0);
    for (int it = 0; it < NIT; it++) {
        CP_WAIT(0);
        __syncthreads();
        if (it + 1 < NIT) issue((it + 1) & 1, (it + 1) * KVROWS);
        const int buf = it & 1;
        #pragma unroll 8
        for (int r = 0; r < KVROWS; r++) {
            float kr[4], vr[4];
            *(float4*)kr = *(const float4*)&ks[buf][r][ty * 4];
            *(float4*)vr = *(const float4*)&vs[buf][r][tx * 4];
            #pragma unroll
            for (int i = 0; i < 4; i++)
                #pragma unroll
                for (int j = 0; j < 4; j++)
                    acc[i][j] += kr[i] * vr[j];
            if (tx == 0) {
                #pragma unroll
                for (int i = 0; i < 4; i++) ksacc[i] += kr[i];
            }
        }
        __syncthreads();
    }

    float* out = g_kv_part + ((size_t)chunk * NBH + bh) * DH * DH;
    #pragma unroll
    for (int i = 0; i < 4; i++)
        #pragma unroll
        for (int j = 0; j < 4; j++)
            out[(ty * 4 + i) * DH + tx * 4 + j] = acc[i][j];
    if (tx == 0) {
        float* ko = g_ksum_part + ((size_t)chunk * NBH + bh) * DH;
        #pragma unroll
        for (int i = 0; i < 4; i++) ko[ty * 4 + i] = ksacc[i];
    }
}

__global__ void kv_final_kernel()
{
    const int bh = blockIdx.x;
    for (int idx = threadIdx.x; idx < DH * DH; idx += blockDim.x) {
        float s = 0.0f;
        #pragma unroll
        for (int c = 0; c < NCHUNK; c++)
            s += g_kv_part[((size_t)c * NBH + bh) * DH * DH + idx];
        g_kv[(size_t)bh * DH * DH + idx] = s;
    }
    for (int idx = threadIdx.x; idx < DH; idx += blockDim.x) {
        float s = 0.0f;
        #pragma unroll
        for (int c = 0; c < NCHUNK; c++)
            s += g_ksum_part[((size_t)c * NBH + bh) * DH + idx];
        g_ksum[(size_t)bh * DH + idx] = s;
    }
}

// ---------------- zq (compacted): q' = z*q*QSCALE -> fp16 ----------------
__global__ __launch_bounds__(256)
void zq_kernel()
{
    const int r = blockIdx.x;
    const int b = r >> 13;
    if ((r & (LL - 1)) >= g_npad[b]) return;

    __shared__ float qrow[DD];
    __shared__ float zs[HH];
    const int tid = threadIdx.x;
    const int wid = tid >> 5, lane = tid & 31;

    const float* qsrc = g_qkv + (size_t)r * N3D;
    ((float4*)qrow)[tid] = ((const float4*)qsrc)[tid];
    __syncthreads();

    #pragma unroll
    for (int hh = 2 * wid; hh < 2 * wid + 2; hh++) {
        const float* ks = g_ksum + ((size_t)b * HH + hh) * DH;
        float v = qrow[hh * DH + lane] * ks[lane]
                + qrow[hh * DH + 32 + lane] * ks[32 + lane];
        #pragma unroll
        for (int o = 16; o > 0; o >>= 1)
            v += __shfl_xor_sync(0xFFFFFFFF, v, o);
        if (lane == 0) zs[hh] = QSCALE / (v + 1e-6f);
    }
    __syncthreads();

    const int c = tid * 4;
    const float z = zs[c >> 6];
    union { __half h[4]; uint2 u; } H;
    #pragma unroll
    for (int j = 0; j < 4; j++)
        H.h[j] = __float2half_rn(qrow[c + j] * z);
    ((uint2*)(g_qph + (size_t)r * DD))[tid] = H.u;
}

// ---------------- M: M_T[b][n][h*64+d] = sum_m kv[b,h,d,m] * Wout[h*64+m, n] -> fp16 ----------------
__global__ __launch_bounds__(256)
void m_kernel(const float* __restrict__ Wout)
{
    __shared__ float kv_s[DH * 65];
    __shared__ float w_s[DH * 64];

    const int bh = blockIdx.x;
    const int b = bh >> 4, h = bh & 15;
    const int n0 = blockIdx.y * 64;
    const int tid = threadIdx.x;

    for (int i = tid; i < DH * DH; i += 256)
        kv_s[(i >> 6) * 65 + (i & 63)] = g_kv[(size_t)bh * DH * DH + i];
    for (int i = tid; i < DH * 64; i += 256) {
        int m = i >> 6, n = i & 63;
        w_s[m * 64 + n] = Wout[(size_t)(h * DH + m) * DD + n0 + n];
    }
    __syncthreads();

    const int d = tid & 63, ng = tid >> 6;
    float acc[16];
    #pragma unroll
    for (int j = 0; j < 16; j++) acc[j] = 0.0f;

    for (int m = 0; m < DH; m++) {
        const float kvd = kv_s[d * 65 + m];
        const float* wr = w_s + m * 64 + ng * 16;
        #pragma unroll
        for (int j = 0; j < 16; j += 4) {
            float4 w4 = *(const float4*)(wr + j);
            acc[j + 0] += kvd * w4.x;
            acc[j + 1] += kvd * w4.y;
            acc[j + 2] += kvd * w4.z;
            acc[j + 3] += kvd * w4.w;
        }
    }

    #pragma unroll
    for (int j = 0; j < 16; j++) {
        const int n = n0 + ng * 16 + j;
        g_mh[((size_t)b * DD + n) * DD + h * DH + d] = __float2half_rn(acc[j]);
    }
}

// ---------------- launch ----------------
extern "C" void kernel_launch(void* const* d_in, const int* in_sizes, int n_in,
                              void* d_out, int out_size)
{
    (void)in_sizes; (void)n_in; (void)out_size;
    const float* x    = (const float*)d_in[0];
    const int*   mask = (const int*)  d_in[1];
    const float* Wqkv = (const float*)d_in[2];
    const float* Wout = (const float*)d_in[3];
    float* out = (float*)d_out;

    __half *xh, *wh, *qph, *mh;
    float *qkv_p;
    cudaGetSymbolAddress((void**)&xh,  g_xh);
    cudaGetSymbolAddress((void**)&wh,  g_wh);
    cudaGetSymbolAddress((void**)&qph, g_qph);
    cudaGetSymbolAddress((void**)&mh,  g_mh);
    cudaGetSymbolAddress((void**)&qkv_p, g_qkv);

    cudaFuncSetAttribute(gemm_fp16<1>, cudaFuncAttributeMaxDynamicSharedMemorySize, SMEM_GEMM);
    cudaFuncSetAttribute(gemm_fp16<2>, cudaFuncAttributeMaxDynamicSharedMemorySize, SMEM_GEMM);

    // order chosen so G1 is the 4th launch (ncu capture slot)
    scan_kernel<<<BB, 1024>>>(mask);
    conv_gather_x<<<MM, 256>>>(x);
    conv_wT<<<dim3(N3D / 32, DD / 32), dim3(32, 8)>>>(Wqkv, wh, DD, N3D);

    // G1: qkv = x_c @ Wqkv (compacted rows)
    gemm_fp16<1><<<dim3(N3D / 128, MM / 128), 128, SMEM_GEMM>>>(
        xh, wh, qkv_p, N3D, DD);

    zero_out<<<MM, 256>>>(mask, out);

    // S2: kv/ksum over compacted rows
    kv_partial_kernel<<<dim3(NBH, NCHUNK), 256>>>();
    kv_final_kernel<<<NBH, 256>>>();

    // z + q' = z*q*QSCALE -> fp16
    zq_kernel<<<MM, 256>>>();

    // M_b^T -> fp16
    m_kernel<<<dim3(NBH, DD / 64), 256>>>(Wout);

    // G2: out[g_idx] = (q' @ M_b) * QSCALE_INV (scatter)
    gemm_fp16<2><<<dim3(DD / 128, MM / 128), 128, SMEM_GEMM>>>(
        qph, mh, out, DD, DD);
}